// round 14
// baseline (speedup 1.0000x reference)
#include <cuda_runtime.h>
#include <cuda_bf16.h>

// SignAdaptor: fused repeat/gather/concat/pad — single kernel, 1 row/CTA,
// 512 threads (warps 0-7: image half, warps 8-15: clip half).
//   out[b, j, 0:1024]    = image_batch[foff[b] + j]                (j < nf[b])
//   out[b, j, 1024:2048] = clip_batch [coff[b] + min(j/rf, nc-1)]  (j < nf[b])
//   out[b, j, :]         = pad_idx                                 (j >= nf[b])
//   src_length[b]        = nf[b]   (appended after x when present)
//
// Write-bandwidth-bound (~156 MB mandatory stores; inputs mostly L2-resident
// across replays; measured ceiling ~5.2 TB/s). 512-thread CTAs halve the CTA
// count vs the 256-thread variant -> half the per-CTA preamble (REDUX offset
// computation) and half the CTA launch/drain overhead, with identical
// coalescing and chip-level memory parallelism.

#define B_CONST 32

__global__ __launch_bounds__(512)
void gather1w_kernel(const float* __restrict__ img,
                     const float* __restrict__ clip,
                     const int* __restrict__ nf,
                     const int* __restrict__ nc,
                     const int* __restrict__ pad,   // may be null -> 0
                     float* __restrict__ out,
                     int L, long long src_off, int has_src) {
    const int j = blockIdx.x;          // frame position within padded length
    const int b = blockIdx.y;          // batch
    const int t = threadIdx.x;         // 0..511
    const int lane = t & 31;
    const int tt = t & 255;            // position within the 1024-float half
    const int is_clip_half = t >> 8;   // warp-uniform: 0 for warps 0-7, 1 for 8-15

    // ---- offsets: sum of nf/nc over samples < b (lane-masked reduction) ----
    const int f_lane = nf[lane];                  // coalesced 128B, L1-hit
    const int c_lane = nc[lane];
    const int foff_b = __reduce_add_sync(0xffffffffu, lane < b ? f_lane : 0);
    const int coff_b = __reduce_add_sync(0xffffffffu, lane < b ? c_lane : 0);
    const int n      = __shfl_sync(0xffffffffu, f_lane, b);
    const int cnum   = __shfl_sync(0xffffffffu, c_lane, b);

    float4* __restrict__ orow =
        (float4*)(out + ((long long)b * L + j) * 2048);

    if (j < n) {
        float4 v;
        if (is_clip_half) {
            const int rf = n / cnum;
            int cidx = j / rf;
            const int cmax = cnum - 1;
            if (cidx > cmax) cidx = cmax;
            const float4* __restrict__ csrc =
                (const float4*)(clip + ((long long)(coff_b + cidx)) * 1024);
            v = csrc[tt];
        } else {
            const float4* __restrict__ isrc =
                (const float4*)(img + ((long long)(foff_b + j)) * 1024);
            v = isrc[tt];
        }
        orow[t] = v;                   // t in 0..511 spans the full 2048-float row
    } else {
        const float pv = pad ? (float)pad[0] : 0.0f;
        orow[t] = make_float4(pv, pv, pv, pv);
    }

    // src_length tail: one thread per batch row (j==0 blocks).
    if (has_src && j == 0 && t == 0) {
        out[src_off + b] = (float)n;
    }
}

extern "C" void kernel_launch(void* const* d_in, const int* in_sizes, int n_in,
                              void* d_out, int out_size) {
    const float* img  = (const float*)d_in[0];   // image_batch [tf, 1024]
    // d_in[1] = emo_batch (unused by reference)
    const float* clip = (const float*)d_in[2];   // clip_batch  [tc, 1024]
    const int*   nf   = (const int*)d_in[3];     // [32]
    const int*   nc   = (const int*)d_in[4];     // [32]
    const int*   pad  = (n_in >= 6) ? (const int*)d_in[5] : nullptr;

    float* out = (float*)d_out;

    // out_size = B*L*2048 (+ B if src_length is part of the flattened output)
    const long long per = (long long)B_CONST * 2048;
    long long L;
    int has_src;
    if ((long long)out_size % per == 0) {
        L = (long long)out_size / per;
        has_src = 0;
    } else {
        L = ((long long)out_size - B_CONST) / per;
        has_src = 1;
    }

    dim3 grid((unsigned)L, B_CONST);
    gather1w_kernel<<<grid, 512>>>(img, clip, nf, nc, pad, out,
                                   (int)L, (long long)B_CONST * L * 2048,
                                   has_src);
}

// round 15
// speedup vs baseline: 1.1469x; 1.1469x over previous
#include <cuda_runtime.h>
#include <cuda_bf16.h>

// SignAdaptor: fused repeat/gather/concat/pad — single kernel, 1 row/CTA.
//   out[b, j, 0:1024]    = image_batch[foff[b] + j]                (j < nf[b])
//   out[b, j, 1024:2048] = clip_batch [coff[b] + min(j/rf, nc-1)]  (j < nf[b])
//   out[b, j, :]         = pad_idx                                 (j >= nf[b])
//   src_length[b]        = nf[b]   (appended after x when present)
//
// FINAL configuration (best measured: kernel 32.96us, 5.18 TB/s DRAM, ~97%
// of the observed write-stream ceiling). Write-bandwidth-bound: ~156 MB
// mandatory stores; inputs mostly L2-resident across replays. 1 row per
// 256-thread CTA (2 float4 per thread) maximizes chip-level memory
// parallelism; prefix offsets via 2 lane-masked REDUX + 2 broadcast SHFL.
// Measured-worse alternatives: RPC=4 batching (flat), CHUNK=16 persistent
// (-14%), 512-thread CTAs (-22%), shuffle-scan preamble (-2%).

#define B_CONST 32

__global__ __launch_bounds__(256)
void gather1_kernel(const float* __restrict__ img,
                    const float* __restrict__ clip,
                    const int* __restrict__ nf,
                    const int* __restrict__ nc,
                    const int* __restrict__ pad,   // may be null -> 0
                    float* __restrict__ out,
                    int L, long long src_off, int has_src) {
    const int j = blockIdx.x;          // frame position within padded length
    const int b = blockIdx.y;          // batch
    const int t = threadIdx.x;         // 0..255
    const int lane = t & 31;

    // ---- offsets: sum of nf/nc over samples < b (lane-masked reduction) ----
    const int f_lane = nf[lane];                  // coalesced 128B, L1-hit
    const int c_lane = nc[lane];
    const int foff_b = __reduce_add_sync(0xffffffffu, lane < b ? f_lane : 0);
    const int coff_b = __reduce_add_sync(0xffffffffu, lane < b ? c_lane : 0);
    const int n      = __shfl_sync(0xffffffffu, f_lane, b);
    const int cnum   = __shfl_sync(0xffffffffu, c_lane, b);

    float4* __restrict__ orow =
        (float4*)(out + ((long long)b * L + j) * 2048);

    if (j < n) {
        const int rf = n / cnum;
        int cidx = j / rf;
        const int cmax = cnum - 1;
        if (cidx > cmax) cidx = cmax;

        const float4* __restrict__ isrc =
            (const float4*)(img + ((long long)(foff_b + j)) * 1024);
        const float4* __restrict__ csrc =
            (const float4*)(clip + ((long long)(coff_b + cidx)) * 1024);

        orow[t]       = isrc[t];
        orow[256 + t] = csrc[t];
    } else {
        const float pv = pad ? (float)pad[0] : 0.0f;
        const float4 p4 = make_float4(pv, pv, pv, pv);
        orow[t]       = p4;
        orow[256 + t] = p4;
    }

    // src_length tail: one thread per batch row (j==0 blocks).
    if (has_src && j == 0 && t == 0) {
        out[src_off + b] = (float)n;
    }
}

extern "C" void kernel_launch(void* const* d_in, const int* in_sizes, int n_in,
                              void* d_out, int out_size) {
    const float* img  = (const float*)d_in[0];   // image_batch [tf, 1024]
    // d_in[1] = emo_batch (unused by reference)
    const float* clip = (const float*)d_in[2];   // clip_batch  [tc, 1024]
    const int*   nf   = (const int*)d_in[3];     // [32]
    const int*   nc   = (const int*)d_in[4];     // [32]
    const int*   pad  = (n_in >= 6) ? (const int*)d_in[5] : nullptr;

    float* out = (float*)d_out;

    // out_size = B*L*2048 (+ B if src_length is part of the flattened output)
    const long long per = (long long)B_CONST * 2048;
    long long L;
    int has_src;
    if ((long long)out_size % per == 0) {
        L = (long long)out_size / per;
        has_src = 0;
    } else {
        L = ((long long)out_size - B_CONST) / per;
        has_src = 1;
    }

    dim3 grid((unsigned)L, B_CONST);
    gather1_kernel<<<grid, 256>>>(img, clip, nf, nc, pad, out,
                                  (int)L, (long long)B_CONST * L * 2048,
                                  has_src);
}

// round 16
// speedup vs baseline: 1.1553x; 1.0073x over previous
#include <cuda_runtime.h>
#include <cuda_bf16.h>

// SignAdaptor: fused repeat/gather/concat/pad — single kernel, 1 row/CTA.
//   out[b, j, 0:1024]    = image_batch[foff[b] + j]                (j < nf[b])
//   out[b, j, 1024:2048] = clip_batch [coff[b] + min(j/rf, nc-1)]  (j < nf[b])
//   out[b, j, :]         = pad_idx                                 (j >= nf[b])
//   src_length[b]        = nf[b]   (appended after x when present)
//
// Best-measured config (kernel ~33.0-33.4us, ~5.1-5.2 TB/s DRAM, ~97% of the
// observed write-stream ceiling). Write-bandwidth-bound: ~156 MB mandatory
// stores; inputs mostly L2-resident across replays. 1 row per 256-thread CTA
// (2 float4 per thread); offsets via 2 lane-masked REDUX + 2 broadcast SHFL.
// This round's single variable: __ldcs on the read-once image stream
// (evict-first) to preserve L2 residency for the 4x-reused clip rows.
// Measured-worse alternatives: RPC=4 (flat), CHUNK=16 persistent (-14%),
// 512-thread CTAs (-22%), shuffle-scan preamble (-2%), .cs stores (in R2 mix).

#define B_CONST 32

__global__ __launch_bounds__(256)
void gather1_kernel(const float* __restrict__ img,
                    const float* __restrict__ clip,
                    const int* __restrict__ nf,
                    const int* __restrict__ nc,
                    const int* __restrict__ pad,   // may be null -> 0
                    float* __restrict__ out,
                    int L, long long src_off, int has_src) {
    const int j = blockIdx.x;          // frame position within padded length
    const int b = blockIdx.y;          // batch
    const int t = threadIdx.x;         // 0..255
    const int lane = t & 31;

    // ---- offsets: sum of nf/nc over samples < b (lane-masked reduction) ----
    const int f_lane = nf[lane];                  // coalesced 128B, L1-hit
    const int c_lane = nc[lane];
    const int foff_b = __reduce_add_sync(0xffffffffu, lane < b ? f_lane : 0);
    const int coff_b = __reduce_add_sync(0xffffffffu, lane < b ? c_lane : 0);
    const int n      = __shfl_sync(0xffffffffu, f_lane, b);
    const int cnum   = __shfl_sync(0xffffffffu, c_lane, b);

    float4* __restrict__ orow =
        (float4*)(out + ((long long)b * L + j) * 2048);

    if (j < n) {
        const int rf = n / cnum;
        int cidx = j / rf;
        const int cmax = cnum - 1;
        if (cidx > cmax) cidx = cmax;

        const float4* __restrict__ isrc =
            (const float4*)(img + ((long long)(foff_b + j)) * 1024);
        const float4* __restrict__ csrc =
            (const float4*)(clip + ((long long)(coff_b + cidx)) * 1024);

        orow[t]       = __ldcs(isrc + t);   // read-once: evict-first in L2
        orow[256 + t] = csrc[t];            // 4x reuse: default caching
    } else {
        const float pv = pad ? (float)pad[0] : 0.0f;
        const float4 p4 = make_float4(pv, pv, pv, pv);
        orow[t]       = p4;
        orow[256 + t] = p4;
    }

    // src_length tail: one thread per batch row (j==0 blocks).
    if (has_src && j == 0 && t == 0) {
        out[src_off + b] = (float)n;
    }
}

extern "C" void kernel_launch(void* const* d_in, const int* in_sizes, int n_in,
                              void* d_out, int out_size) {
    const float* img  = (const float*)d_in[0];   // image_batch [tf, 1024]
    // d_in[1] = emo_batch (unused by reference)
    const float* clip = (const float*)d_in[2];   // clip_batch  [tc, 1024]
    const int*   nf   = (const int*)d_in[3];     // [32]
    const int*   nc   = (const int*)d_in[4];     // [32]
    const int*   pad  = (n_in >= 6) ? (const int*)d_in[5] : nullptr;

    float* out = (float*)d_out;

    // out_size = B*L*2048 (+ B if src_length is part of the flattened output)
    const long long per = (long long)B_CONST * 2048;
    long long L;
    int has_src;
    if ((long long)out_size % per == 0) {
        L = (long long)out_size / per;
        has_src = 0;
    } else {
        L = ((long long)out_size - B_CONST) / per;
        has_src = 1;
    }

    dim3 grid((unsigned)L, B_CONST);
    gather1_kernel<<<grid, 256>>>(img, clip, nf, nc, pad, out,
                                  (int)L, (long long)B_CONST * L * 2048,
                                  has_src);
}